// round 10
// baseline (speedup 1.0000x reference)
#include <cuda_runtime.h>
#include <cuda_bf16.h>
#include <math.h>
#include <stdint.h>

#define BB    64
#define TT    2048
#define ENCD  512
#define DECD  1024
#define CONVC 32
#define KW    31
#define HID   256
#define PADW  15

#define NSTAGE 9              // 8 enc K-blocks of 64 + 1 conv block (zero-padded to 64)
#define KBLK   64
#define TILE_T 128
#define WTILE_ELEMS (HID * KBLK)   // 16384 bf16 per stage tile (full 256 h)

// ---------------- helpers ----------------
__device__ __forceinline__ uint32_t smem_u32(const void* p) {
    uint32_t a;
    asm("{ .reg .u64 t; cvta.to.shared.u64 t, %1; cvt.u32.u64 %0, t; }" : "=r"(a) : "l"(p));
    return a;
}
__device__ __forceinline__ uint32_t sw128(uint32_t x) { return x ^ ((x >> 3) & 0x70); }

__device__ __forceinline__ void ldsm_x4(uint32_t* r, uint32_t addr) {
    asm volatile("ldmatrix.sync.aligned.m8n8.x4.shared.b16 {%0,%1,%2,%3}, [%4];"
                 : "=r"(r[0]), "=r"(r[1]), "=r"(r[2]), "=r"(r[3]) : "r"(addr));
}
__device__ __forceinline__ void mma16816(float* c, const uint32_t* a, const uint32_t* b) {
    asm volatile("mma.sync.aligned.m16n8k16.row.col.f32.bf16.bf16.f32 "
                 "{%0,%1,%2,%3}, {%4,%5,%6,%7}, {%8,%9}, {%0,%1,%2,%3};"
                 : "+f"(c[0]), "+f"(c[1]), "+f"(c[2]), "+f"(c[3])
                 : "r"(a[0]), "r"(a[1]), "r"(a[2]), "r"(a[3]), "r"(b[0]), "r"(b[1]));
}

// ---------------- device scratch ----------------
__device__ __align__(256) __nv_bfloat16 g_Wb1[NSTAGE * WTILE_ELEMS];  // hi tiles, pre-swizzled [h][k]
__device__ __align__(256) __nv_bfloat16 g_Wb2[NSTAGE * WTILE_ELEMS];  // lo tiles, pre-swizzled
__device__ float g_Mt[KW * HID];         // (W_att @ conv_w): [k][h]
__device__ float g_dec[BB * HID];        // dec_state @ W_dec^T
__device__ float g_bw[2 * HID];          // [0:HID)=b_enc, [HID:2HID)=w_w
__device__ float g_epart[2 * BB * TT];   // per-hblock partial energies

// ---------------- prep kernels ----------------
__global__ void k_M(const float* __restrict__ W_att, const float* __restrict__ conv_w) {
    int h = threadIdx.x;
    for (int k = 0; k < KW; k++) {
        float s = 0.f;
        for (int c = 0; c < CONVC; c++) s += W_att[h * CONVC + c] * conv_w[c * KW + k];
        g_Mt[k * HID + h] = s;
    }
}

// Build swizzled bf16 split weight tiles: stage s tile = [h=0..255][k=0..63], 128B rows, SW128
__global__ void k_prepW(const float* __restrict__ W_enc) {
    int idx = blockIdx.x * 256 + threadIdx.x;
    int s = idx / WTILE_ELEMS;
    int r = idx - s * WTILE_ELEMS;
    int h = r / KBLK;
    int k = r - h * KBLK;
    float v;
    if (s < 8) v = W_enc[h * ENCD + s * KBLK + k];
    else       v = (k < KW) ? g_Mt[k * HID + h] : 0.f;
    __nv_bfloat16 hi = __float2bfloat16(v);
    __nv_bfloat16 lo = __float2bfloat16(v - __bfloat162float(hi));
    uint32_t swo = sw128((uint32_t)h * 128 + (uint32_t)k * 2);
    *(__nv_bfloat16*)((char*)g_Wb1 + (size_t)s * 32768 + swo) = hi;
    *(__nv_bfloat16*)((char*)g_Wb2 + (size_t)s * 32768 + swo) = lo;
}

__global__ void k_prepBW(const float* __restrict__ b_enc, const float* __restrict__ w_w) {
    int i = threadIdx.x;
    g_bw[i] = b_enc[i];
    g_bw[HID + i] = w_w[i];
}

__global__ void k_dec(const float* __restrict__ W_dec, const float* __restrict__ dec_state) {
    int b = blockIdx.x, h = threadIdx.x;
    const float4* w4 = (const float4*)(W_dec + h * DECD);
    const float4* d4 = (const float4*)(dec_state + b * DECD);
    float s = 0.f;
    for (int i = 0; i < DECD / 4; i++) {
        float4 w = w4[i]; float4 d = d4[i];
        s += w.x * d.x + w.y * d.y + w.z * d.z + w.w * d.w;
    }
    g_dec[b * HID + h] = s;
}

// ---------------- tensor-core (mma.sync) energy kernel ----------------
// CTA tile: 128 t x 128 h (h half selected by blockIdx.y). 8 warps in 4(M)x2(N).
// SMEM byte offsets (dynamic)
#define SM_A1   0
#define SM_A2   16384
#define SM_B1   32768
#define SM_B2   49152
#define SM_EP   65536
#define SM_TOTAL (SM_EP + 1024)   // 66560

__global__ __launch_bounds__(256)
void k_energy_mma(const float* __restrict__ enc, const float* __restrict__ prev) {
    extern __shared__ char smem[];
    const uint32_t sb = smem_u32(smem);
    const int tid = threadIdx.x, lane = tid & 31, wid = tid >> 5;
    const int mw = wid & 3, nw = wid >> 2;         // warp grid 4(M) x 2(N)
    const int hb = blockIdx.y;                     // h half: 0 or 1
    const int b  = blockIdx.z;
    const int t0 = blockIdx.x * TILE_T;

    const int ar  = tid >> 1;                      // A fill row 0..127
    const int akh = (tid & 1) * 32;                // k half base

    float acc[2][8][4];
#pragma unroll
    for (int mi = 0; mi < 2; mi++)
#pragma unroll
        for (int nj = 0; nj < 8; nj++)
#pragma unroll
            for (int q = 0; q < 4; q++) acc[mi][nj][q] = 0.f;

    // ldmatrix lane-dependent address components (canonical maps)
    const int a_row_in = lane & 15;
    const int a_khalf  = lane >> 4;
    const int b_jj     = lane >> 4;
    const int b_khalf  = (lane >> 3) & 1;
    const int b_row    = lane & 7;

    for (int s = 0; s < NSTAGE; s++) {
        if (s) __syncthreads();

        // ---- A tile fill: 128 x 64 fp32 -> bf16 hi/lo, SW128 ----
#pragma unroll
        for (int q = 0; q < 8; q++) {
            float4 v;
            if (s < 8) {
                v = *(const float4*)(enc + ((size_t)b * TT + t0 + ar) * ENCD + s * KBLK + akh + q * 4);
            } else {
                float vv[4];
#pragma unroll
                for (int i = 0; i < 4; i++) {
                    int j = akh + q * 4 + i;
                    int t = t0 + ar + j - PADW;
                    vv[i] = (j < KW && t >= 0 && t < TT) ? prev[b * TT + t] : 0.f;
                }
                v = make_float4(vv[0], vv[1], vv[2], vv[3]);
            }
            float x[4] = {v.x, v.y, v.z, v.w};
            uint64_t hi64 = 0, lo64 = 0;
#pragma unroll
            for (int i = 0; i < 4; i++) {
                __nv_bfloat16 h1 = __float2bfloat16(x[i]);
                __nv_bfloat16 h2 = __float2bfloat16(x[i] - __bfloat162float(h1));
                hi64 |= (uint64_t)__bfloat16_as_ushort(h1) << (16 * i);
                lo64 |= (uint64_t)__bfloat16_as_ushort(h2) << (16 * i);
            }
            uint32_t swo = sw128((uint32_t)ar * 128 + (uint32_t)(akh + q * 4) * 2);
            *(uint64_t*)(smem + SM_A1 + swo) = hi64;
            *(uint64_t*)(smem + SM_A2 + swo) = lo64;
        }

        // ---- B tiles: this CTA's 128-h half, 16KB per term, linear copy ----
        {
            const uint4* sB1 = (const uint4*)g_Wb1 + (size_t)s * 2048 + hb * 1024;
            const uint4* sB2 = (const uint4*)g_Wb2 + (size_t)s * 2048 + hb * 1024;
#pragma unroll
            for (int q = 0; q < 4; q++) {
                ((uint4*)(smem + SM_B1))[tid + q * 256] = sB1[tid + q * 256];
                ((uint4*)(smem + SM_B2))[tid + q * 256] = sB2[tid + q * 256];
            }
        }
        __syncthreads();

        // ---- compute: 4 k16 steps ----
#pragma unroll
        for (int ks = 0; ks < 4; ks++) {
            const int kb = ks * 16;
            uint32_t a1[2][4], a2[2][4];
#pragma unroll
            for (int mi = 0; mi < 2; mi++) {
                uint32_t ro = (uint32_t)(mw * 32 + mi * 16 + a_row_in) * 128
                            + (uint32_t)(kb + a_khalf * 8) * 2;
                uint32_t swo = sw128(ro);
                ldsm_x4(a1[mi], sb + SM_A1 + swo);
                ldsm_x4(a2[mi], sb + SM_A2 + swo);
            }
            uint32_t bf[4][4];
            uint32_t bro = (uint32_t)(nw * 64 + b_jj * 8 + b_row) * 128
                         + (uint32_t)(kb + b_khalf * 8) * 2;
            // B1 term: A1*B1 and A2*B1
#pragma unroll
            for (int p = 0; p < 4; p++)
                ldsm_x4(bf[p], sb + SM_B1 + sw128(bro + (uint32_t)p * 16 * 128));
#pragma unroll
            for (int mi = 0; mi < 2; mi++)
#pragma unroll
                for (int nj = 0; nj < 8; nj++)
                    mma16816(acc[mi][nj], a1[mi], &bf[nj >> 1][(nj & 1) * 2]);
#pragma unroll
            for (int mi = 0; mi < 2; mi++)
#pragma unroll
                for (int nj = 0; nj < 8; nj++)
                    mma16816(acc[mi][nj], a2[mi], &bf[nj >> 1][(nj & 1) * 2]);
            // B2 term: A1*B2
#pragma unroll
            for (int p = 0; p < 4; p++)
                ldsm_x4(bf[p], sb + SM_B2 + sw128(bro + (uint32_t)p * 16 * 128));
#pragma unroll
            for (int mi = 0; mi < 2; mi++)
#pragma unroll
                for (int nj = 0; nj < 8; nj++)
                    mma16816(acc[mi][nj], a1[mi], &bf[nj >> 1][(nj & 1) * 2]);
        }
    }

    // ---- epilogue: per-thread constants from global (tiny, cached) ----
    float dd[8][2], wv[8][2];
#pragma unroll
    for (int nj = 0; nj < 8; nj++) {
        int hh = hb * 128 + nw * 64 + nj * 8 + (lane & 3) * 2;
        dd[nj][0] = g_dec[b * HID + hh]     + g_bw[hh];
        dd[nj][1] = g_dec[b * HID + hh + 1] + g_bw[hh + 1];
        wv[nj][0] = g_bw[HID + hh];
        wv[nj][1] = g_bw[HID + hh + 1];
    }

    float* ep = (float*)(smem + SM_EP);
    __syncthreads();
#pragma unroll
    for (int mi = 0; mi < 2; mi++) {
#pragma unroll
        for (int half = 0; half < 2; half++) {
            float e = 0.f;
#pragma unroll
            for (int nj = 0; nj < 8; nj++) {
                e += wv[nj][0] * tanhf(acc[mi][nj][half * 2 + 0] + dd[nj][0]);
                e += wv[nj][1] * tanhf(acc[mi][nj][half * 2 + 1] + dd[nj][1]);
            }
            e += __shfl_xor_sync(0xffffffffu, e, 1);
            e += __shfl_xor_sync(0xffffffffu, e, 2);
            if ((lane & 3) == 0)
                ep[nw * 128 + mw * 32 + mi * 16 + half * 8 + (lane >> 2)] = e;
        }
    }
    __syncthreads();
    if (tid < 128) {
        float e = ep[tid] + ep[128 + tid];
        g_epart[(size_t)hb * BB * TT + (size_t)b * TT + t0 + tid] = e;
    }
}

// ---------------- softmax over T per batch (sums partials, adds w_b, masks) ----------------
__global__ void k_softmax(const int* __restrict__ text_len, const float* __restrict__ w_b,
                          float* __restrict__ attw_out) {
    __shared__ float red[256];
    const int b = blockIdx.x, tid = threadIdx.x;
    const int tl = text_len[b];
    const float wb = w_b[0];
    float v[8];
    float m = __int_as_float(0xff800000u);
#pragma unroll
    for (int i = 0; i < 8; i++) {
        int t = tid + i * 256;
        float e = g_epart[(size_t)b * TT + t] + g_epart[(size_t)BB * TT + (size_t)b * TT + t] + wb;
        v[i] = (t >= tl) ? __int_as_float(0xff800000u) : e;
        m = fmaxf(m, v[i]);
    }
    red[tid] = m; __syncthreads();
    for (int s = 128; s > 0; s >>= 1) { if (tid < s) red[tid] = fmaxf(red[tid], red[tid + s]); __syncthreads(); }
    const float mx = red[0]; __syncthreads();
    float sum = 0.f;
#pragma unroll
    for (int i = 0; i < 8; i++) { v[i] = expf(v[i] - mx); sum += v[i]; }
    red[tid] = sum; __syncthreads();
    for (int s = 128; s > 0; s >>= 1) { if (tid < s) red[tid] += red[tid + s]; __syncthreads(); }
    const float inv = 1.f / red[0];
#pragma unroll
    for (int i = 0; i < 8; i++) attw_out[b * TT + tid + i * 256] = v[i] * inv;
}

// ---------------- context: att_c[b][e] = sum_t attw[b][t]*enc[b][t][e] ----------------
__global__ __launch_bounds__(256)
void k_attc(const float* __restrict__ enc, const float* __restrict__ attw, float* __restrict__ out) {
    __shared__ float sw[TT];
    const int b = blockIdx.y, tid = threadIdx.x;
    const int e = blockIdx.x * 256 + tid;
#pragma unroll
    for (int i = 0; i < 8; i++) sw[tid + i * 256] = attw[b * TT + tid + i * 256];
    __syncthreads();
    const float* ep = enc + (size_t)b * TT * ENCD + e;
    float a0 = 0.f, a1 = 0.f, a2 = 0.f, a3 = 0.f, a4 = 0.f, a5 = 0.f, a6 = 0.f, a7 = 0.f;
    for (int t = 0; t < TT; t += 8) {
        a0 = fmaf(sw[t + 0], ep[(size_t)(t + 0) * ENCD], a0);
        a1 = fmaf(sw[t + 1], ep[(size_t)(t + 1) * ENCD], a1);
        a2 = fmaf(sw[t + 2], ep[(size_t)(t + 2) * ENCD], a2);
        a3 = fmaf(sw[t + 3], ep[(size_t)(t + 3) * ENCD], a3);
        a4 = fmaf(sw[t + 4], ep[(size_t)(t + 4) * ENCD], a4);
        a5 = fmaf(sw[t + 5], ep[(size_t)(t + 5) * ENCD], a5);
        a6 = fmaf(sw[t + 6], ep[(size_t)(t + 6) * ENCD], a6);
        a7 = fmaf(sw[t + 7], ep[(size_t)(t + 7) * ENCD], a7);
    }
    out[b * ENCD + e] = ((a0 + a1) + (a2 + a3)) + ((a4 + a5) + (a6 + a7));
}

// ---------------- launch ----------------
extern "C" void kernel_launch(void* const* d_in, const int* in_sizes, int n_in,
                              void* d_out, int out_size) {
    const float* enc       = (const float*)d_in[0];
    const float* dec_state = (const float*)d_in[1];
    const float* prev      = (const float*)d_in[2];
    const int*   text_len  = (const int*)  d_in[3];
    const float* W_enc     = (const float*)d_in[4];
    const float* b_enc     = (const float*)d_in[5];
    const float* W_dec     = (const float*)d_in[6];
    const float* W_att     = (const float*)d_in[7];
    const float* conv_w    = (const float*)d_in[8];
    const float* w_w       = (const float*)d_in[9];
    const float* w_b       = (const float*)d_in[10];

    float* out      = (float*)d_out;          // att_c: [B, ENC]
    float* out_attw = out + BB * ENCD;        // att_w: [B, T]

    cudaFuncSetAttribute(k_energy_mma, cudaFuncAttributeMaxDynamicSharedMemorySize, SM_TOTAL);

    k_M<<<1, 256>>>(W_att, conv_w);
    k_prepW<<<(NSTAGE * WTILE_ELEMS) / 256, 256>>>(W_enc);
    k_prepBW<<<1, 256>>>(b_enc, w_w);
    k_dec<<<BB, 256>>>(W_dec, dec_state);
    k_energy_mma<<<dim3(TT / TILE_T, 2, BB), 256, SM_TOTAL>>>(enc, prev);
    k_softmax<<<BB, 256>>>(text_len, w_b, out_attw);
    k_attc<<<dim3(ENCD / 256, BB), 256>>>(enc, out_attw, out);
}